// round 17
// baseline (speedup 1.0000x reference)
#include <cuda_runtime.h>
#include <cuda_fp16.h>
#include <math.h>
#include <stdint.h>

#define N_PTS 32768
typedef uint32_t u32;

// ---------------- scratch (device globals; no allocations allowed) ----------
__device__ float g_bufA[N_PTS * 256];
__device__ float g_bufB[N_PTS * 256];
__device__ __align__(16) __half g_W0[256 * 288];
__device__ __align__(16) __half g_W1[256 * 2304];
__device__ __align__(16) __half g_W2[256 * 2304];
__device__ float g_w3[2304];

// ---------------- PTX helpers (compute_80-era, arch-neutral) -----------------
__device__ __forceinline__ u32 smem_u32(const void* p) {
    u32 a;
    asm("{ .reg .u64 t; cvta.to.shared.u64 t, %1; cvt.u32.u64 %0, t; }"
        : "=r"(a) : "l"(p));
    return a;
}
__device__ __forceinline__ void ldsm_x4(u32* r, u32 addr) {
    asm volatile("ldmatrix.sync.aligned.m8n8.x4.shared.b16 {%0,%1,%2,%3}, [%4];"
                 : "=r"(r[0]), "=r"(r[1]), "=r"(r[2]), "=r"(r[3]) : "r"(addr));
}
__device__ __forceinline__ void mma_f16(float* c, const u32* a, const u32* b) {
    asm volatile(
        "mma.sync.aligned.m16n8k16.row.col.f32.f16.f16.f32 "
        "{%0,%1,%2,%3}, {%4,%5,%6,%7}, {%8,%9}, {%0,%1,%2,%3};"
        : "+f"(c[0]), "+f"(c[1]), "+f"(c[2]), "+f"(c[3])
        : "r"(a[0]), "r"(a[1]), "r"(a[2]), "r"(a[3]), "r"(b[0]), "r"(b[1]));
}
__device__ __forceinline__ void cp16(u32 dst, const void* src) {
    asm volatile("cp.async.cg.shared.global [%0], [%1], 16;"
                 :: "r"(dst), "l"(src) : "memory");
}

// ---------------- closed-form cubic B-spline (uniform knots) -----------------
__device__ __forceinline__ void bspline8(float t, float* bb) {
    float u = (t + 2.2f) * 2.5f;
    float fj = floorf(u);
    int jc = (int)fj;
    float w = u - fj;
    float om = 1.0f - w;
    float w2 = w * w, w3 = w2 * w;
    float p0 = om * om * om * (1.0f / 6.0f);
    float p1 = (3.0f * w3 - 6.0f * w2 + 4.0f) * (1.0f / 6.0f);
    float p2 = (-3.0f * w3 + 3.0f * w2 + 3.0f * w + 1.0f) * (1.0f / 6.0f);
    float p3 = w3 * (1.0f / 6.0f);
#pragma unroll
    for (int i = 0; i < 8; i++) {
        int m = i - jc + 3;
        float v = (m == 0) ? p0 : (m == 1) ? p1 : (m == 2) ? p2 : (m == 3) ? p3 : 0.0f;
        bb[i] = v;
    }
}
__device__ __forceinline__ float silu_f(float v) {
    return v * (1.0f / (1.0f + __expf(-v)));
}

// ---------------- fused weight prep (single launch) --------------------------
// K layout PERMUTED per 144-chunk: k = c*144 + j*16 + fl, feature f = c*16+fl.
__device__ __forceinline__ void prep_one(const float* bw, const float* sw,
                                         const float* ss, __half* W,
                                         int F, int idx) {
    int K = 9 * F;
    if (idx >= 256 * K) return;
    int o = idx / K, k = idx - o * K;
    int c = k / 144, r = k - c * 144;
    int j = r >> 4, fl = r & 15;
    int f = c * 16 + fl;
    float v = (j == 0) ? bw[o * F + f] : sw[(o * F + f) * 8 + (j - 1)] * ss[o * F + f];
    W[idx] = __float2half_rn(v);
}
__global__ void prep_all(const float* __restrict__ bw0, const float* __restrict__ sw0, const float* __restrict__ ss0,
                         const float* __restrict__ bw1, const float* __restrict__ sw1, const float* __restrict__ ss1,
                         const float* __restrict__ bw2, const float* __restrict__ sw2, const float* __restrict__ ss2,
                         const float* __restrict__ bw3, const float* __restrict__ sw3, const float* __restrict__ ss3,
                         __half* __restrict__ W0, __half* __restrict__ W1, __half* __restrict__ W2,
                         float* __restrict__ w3) {
    int b = blockIdx.x, t = threadIdx.x;
    if (b < 288) {
        prep_one(bw0, sw0, ss0, W0, 32, b * 256 + t);
    } else if (b < 2592) {
        prep_one(bw1, sw1, ss1, W1, 256, (b - 288) * 256 + t);
    } else if (b < 4896) {
        prep_one(bw2, sw2, ss2, W2, 256, (b - 2592) * 256 + t);
    } else {
        int k = (b - 4896) * 256 + t;
        if (k < 2304) {
            int f = k / 9, j = k - f * 9;
            w3[k] = (j == 0) ? bw3[f] : sw3[f * 8 + (j - 1)] * ss3[f];
        }
    }
}

// ---------------- positional encoding ---------------------------------------
__global__ void encode_kernel(const float* __restrict__ x,
                              const float* __restrict__ freq,
                              float* __restrict__ h0) {
    int idx = blockIdx.x * blockDim.x + threadIdx.x;
    if (idx >= N_PTS * 16) return;
    int n = idx >> 4, j = idx & 15;
    float enc = x[n] * freq[j];
    double ed = (double)enc;
    double q = rint(ed * 0.15915494309189535);
    double rd = fma(-q, 6.283185307179586, ed);
    float r = (float)rd;
    float s, c;
    __sincosf(r, &s, &c);
    h0[n * 32 + j] = s;
    h0[n * 32 + 16 + j] = c;
}

// ---------------- smem swizzle: row stride 288 B (18 x 16B units) ------------
__device__ __forceinline__ u32 swz_off(int row, int u) {
    if (u < 16) return (u32)(row * 288 + ((u * 16) ^ ((row & 7) * 16)));
    return (u32)(row * 288 + 256 + (((u ^ row) & 1) * 16));
}

// ---------------- fused HMMA KAN layer, 512 thr, 2 CTAs/SM, A dbl-buffer -----
// Single fp16 term. CTA tile: 64 rows x 256 cols. K chunks of 144 (k=j*16+fl).
// 16 warps: 2 m-groups x 8 n-groups, warp tile 32x32.
// smem per CTA (110592 B): A0@0 A1@18432 W@36864 -> 2 CTAs/SM = 8 warps/SMSP.
// A(c+1) is produced INSIDE chunk c's MMA loop (from prefetched LDGs) into the
// alternate A buffer; serial region holds only the W cp.async + barriers.
template <int F>
__global__ void __launch_bounds__(512, 2)
kan_hmma(const float* __restrict__ hin, const __half* __restrict__ Wg,
         float* __restrict__ out) {
    constexpr int K = 9 * F, NCH = K / 144;
    constexpr u32 ABUF = 18432, WO = 36864;
    extern __shared__ __align__(16) char smem[];
    const u32 sbase = smem_u32(smem);

    const int tid = threadIdx.x;
    const int lane = tid & 31, warp = tid >> 5;
    const int wm = (warp & 1) * 32;              // 2 m-groups of 32 rows
    const int wn = (warp >> 1) * 32;             // 8 n-groups of 32 cols
    const int row0 = blockIdx.x * 64;

    int rowA[2], rowB[2];
    const int bitA = lane >> 4;
    const int bitB = (lane >> 3) & 1;
#pragma unroll
    for (int mi = 0; mi < 2; mi++) rowA[mi] = wm + mi * 16 + (lane & 15);
#pragma unroll
    for (int jj = 0; jj < 2; jj++) rowB[jj] = wn + jj * 16 + (lane & 7) + ((lane >> 4) << 3);

    // 2 A-items per thread: id = tid + 512*i -> fl = id&15, row = id>>4 (0..63)
    const int fl0 = tid & 15,          rA0 = tid >> 4;
    const int fl1 = (tid + 512) & 15,  rA1 = (tid + 512) >> 4;

    float acc[2][4][4];
#pragma unroll
    for (int mi = 0; mi < 2; mi++)
#pragma unroll
        for (int nf = 0; nf < 4; nf++)
#pragma unroll
            for (int q = 0; q < 4; q++) acc[mi][nf][q] = 0.0f;

    // ---- helpers
    auto issueW = [&](int c) {
#pragma unroll
        for (int i = 0; i < 9; i++) {
            int u = tid + 512 * i;
            int row = u / 18, pos = u - row * 18;
            size_t gi = ((size_t)row * K + c * 144) / 8 + pos;
            cp16(sbase + WO + swz_off(row, pos),
                 reinterpret_cast<const uint4*>(Wg) + gi);
        }
    };
    auto storeA = [&](float t, int fl, int row, u32 abase) {
        float v[9];
        v[0] = silu_f(t);
        bspline8(t, v + 1);
        const int ub = fl >> 3, bo = (fl & 7) * 2;
#pragma unroll
        for (int j = 0; j < 9; j++) {
            u32 off = swz_off(row, 2 * j + ub) + bo;
            *reinterpret_cast<__half*>(smem + abase + off) = __float2half_rn(v[j]);
        }
    };

    // ---- prologue: produce A(0) into buffer 0 (from fresh LDGs)
    {
        float p0 = hin[(size_t)(row0 + rA0) * F + fl0];
        float p1 = hin[(size_t)(row0 + rA1) * F + fl1];
        storeA(p0, fl0, rA0, 0);
        storeA(p1, fl1, rA1, 0);
    }

    for (int c = 0; c < NCH; c++) {
        const u32 aoff = (u32)(c & 1) * ABUF;       // MMA reads this buffer
        const u32 noff = (u32)((c + 1) & 1) * ABUF; // next A written here
        __syncthreads();                    // all warps done MMA(c-1) (W + A safe)
        issueW(c);
        asm volatile("cp.async.commit_group;" ::: "memory");
        asm volatile("cp.async.wait_group 0;" ::: "memory");
        __syncthreads();                    // W(c) + A(c) visible to all warps
        const bool more = (c + 1 < NCH);
        float t0 = 0.0f, t1 = 0.0f;
        if (more) {
            // prefetch next-chunk activations (consumed at ks 5/7 below)
            t0 = hin[(size_t)(row0 + rA0) * F + (c + 1) * 16 + fl0];
            t1 = hin[(size_t)(row0 + rA1) * F + (c + 1) * 16 + fl1];
        }
#pragma unroll
        for (int ks = 0; ks < 9; ks++) {
            u32 ah[2][4], b[2][4];
#pragma unroll
            for (int mi = 0; mi < 2; mi++)
                ldsm_x4(ah[mi], sbase + aoff + swz_off(rowA[mi], 2 * ks + bitA));
#pragma unroll
            for (int jj = 0; jj < 2; jj++)
                ldsm_x4(b[jj], sbase + WO + swz_off(rowB[jj], 2 * ks + bitB));
#pragma unroll
            for (int mi = 0; mi < 2; mi++)
#pragma unroll
                for (int nf = 0; nf < 4; nf++)
                    mma_f16(acc[mi][nf], ah[mi], &b[nf >> 1][(nf & 1) * 2]);
            // produce next chunk's A under the MMA window (alternate buffer)
            if (more && ks == 5) storeA(t0, fl0, rA0, noff);
            if (more && ks == 7) storeA(t1, fl1, rA1, noff);
        }
    }
    // ---- epilogue: c-frag direct stores
#pragma unroll
    for (int mi = 0; mi < 2; mi++)
#pragma unroll
        for (int nf = 0; nf < 4; nf++) {
            int r0 = row0 + wm + mi * 16 + (lane >> 2);
            int cc = wn + nf * 8 + (lane & 3) * 2;
            *reinterpret_cast<float2*>(&out[(size_t)r0 * 256 + cc]) =
                make_float2(acc[mi][nf][0], acc[mi][nf][1]);
            *reinterpret_cast<float2*>(&out[(size_t)(r0 + 8) * 256 + cc]) =
                make_float2(acc[mi][nf][2], acc[mi][nf][3]);
        }
}

// ---------------- last layer: O = 1 ------------------------------------------
__global__ void kan_last(const float* __restrict__ hin,
                         const float* __restrict__ W,
                         float* __restrict__ out) {
    __shared__ float Ws[2304];
    int tid = threadIdx.x;
#pragma unroll
    for (int i = tid; i < 2304; i += 256) Ws[i] = W[i];
    __syncthreads();
    int warp = tid >> 5, lane = tid & 31;
    int n = blockIdx.x * 8 + warp;
    float sum = 0.0f;
#pragma unroll
    for (int ff = 0; ff < 8; ff++) {
        int f = ff * 32 + lane;
        float t = hin[n * 256 + f];
        float bb[8];
        bspline8(t, bb);
        float sl = silu_f(t) * Ws[f * 9];
#pragma unroll
        for (int j = 0; j < 8; j++) sl += bb[j] * Ws[f * 9 + 1 + j];
        sum += sl;
    }
#pragma unroll
    for (int off = 16; off; off >>= 1)
        sum += __shfl_xor_sync(0xffffffffu, sum, off);
    if (lane == 0) out[n] = sum;
}

// ---------------- launch ------------------------------------------------------
extern "C" void kernel_launch(void* const* d_in, const int* in_sizes, int n_in,
                              void* d_out, int out_size) {
    const float* x    = (const float*)d_in[0];
    const float* freq = (const float*)d_in[1];
    const float* bw0  = (const float*)d_in[2];
    const float* sw0  = (const float*)d_in[3];
    const float* ss0  = (const float*)d_in[4];
    const float* bw1  = (const float*)d_in[5];
    const float* sw1  = (const float*)d_in[6];
    const float* ss1  = (const float*)d_in[7];
    const float* bw2  = (const float*)d_in[8];
    const float* sw2  = (const float*)d_in[9];
    const float* ss2  = (const float*)d_in[10];
    const float* bw3  = (const float*)d_in[11];
    const float* sw3  = (const float*)d_in[12];
    const float* ss3  = (const float*)d_in[13];
    float* out = (float*)d_out;

    float *bufA, *bufB, *w3;
    __half *W0, *W1, *W2;
    cudaGetSymbolAddress((void**)&bufA, g_bufA);
    cudaGetSymbolAddress((void**)&bufB, g_bufB);
    cudaGetSymbolAddress((void**)&W0, g_W0);
    cudaGetSymbolAddress((void**)&W1, g_W1);
    cudaGetSymbolAddress((void**)&W2, g_W2);
    cudaGetSymbolAddress((void**)&w3, g_w3);

    const int SMEM = 110592;
    cudaFuncSetAttribute(kan_hmma<32>,  cudaFuncAttributeMaxDynamicSharedMemorySize, SMEM);
    cudaFuncSetAttribute(kan_hmma<256>, cudaFuncAttributeMaxDynamicSharedMemorySize, SMEM);

    // [0] all weight prep in one launch
    prep_all<<<4905, 256>>>(bw0, sw0, ss0, bw1, sw1, ss1, bw2, sw2, ss2,
                            bw3, sw3, ss3, W0, W1, W2, w3);
    // [1] encoding
    encode_kernel<<<(N_PTS * 16) / 256, 256>>>(x, freq, bufA);

    // [2] layer 0
    kan_hmma<32><<<N_PTS / 64, 512, SMEM>>>(bufA, W0, bufB);
    // [3] layer 1  (<- ncu capture slot)
    kan_hmma<256><<<N_PTS / 64, 512, SMEM>>>(bufB, W1, bufA);
    // [4] layer 2
    kan_hmma<256><<<N_PTS / 64, 512, SMEM>>>(bufA, W2, bufB);
    // [5] last layer
    kan_last<<<N_PTS / 8, 256>>>(bufB, w3, out);
}